// round 1
// baseline (speedup 1.0000x reference)
#include <cuda_runtime.h>
#include <cuda_bf16.h>
#include <cstdint>

#define MAX_N 50000
#define HIDN 128

// ---------------- scratch (no allocations allowed) ----------------
__device__ float d_hp  [(size_t)MAX_N * HIDN];
__device__ float d_agg [(size_t)MAX_N * HIDN];
__device__ float d_t   [(size_t)MAX_N * HIDN];
__device__ float d_outl[(size_t)3 * MAX_N * HIDN];
__device__ float d_zcat[256 * 768];
__device__ float d_zh  [256 * 128];
__device__ float d_stats[256];
__device__ float d_scale[128];
__device__ float d_shift[128];

// ---------------- GEMM: C[M x 128] = f(A[M x K]) @ W[K x 128] + bias ----------------
// mode 0: f(A)=A ; mode 1: f(A)=A+A2 ; mode 2: f(A)=relu(A*scale[k]+shift[k]) (per-K-column affine)
__global__ __launch_bounds__(256) void gemm_kernel(
    const float* __restrict__ A, const float* __restrict__ A2,
    const float* __restrict__ scale, const float* __restrict__ shift,
    const float* __restrict__ W, const float* __restrict__ bias,
    float* __restrict__ C, int M, int K, int mode)
{
    constexpr int BM = 64, BN = 128, BK = 32;
    __shared__ __align__(16) float As[BM][BK + 1];
    __shared__ __align__(16) float Bs[BK][BN];

    const int tid = threadIdx.x;
    const int m0 = blockIdx.x * BM;
    const int tx = tid & 15;        // 16 col-groups of 8
    const int ty = tid >> 4;        // 16 row-groups of 4

    float acc[4][8];
    #pragma unroll
    for (int i = 0; i < 4; i++)
        #pragma unroll
        for (int j = 0; j < 8; j++) acc[i][j] = 0.f;

    for (int kb = 0; kb < K; kb += BK) {
        // load A tile (64x32) -> 512 float4, 2 per thread
        #pragma unroll
        for (int i = 0; i < 2; i++) {
            int idx = tid + i * 256;
            int r = idx >> 3, c4 = idx & 7;
            int gr = m0 + r;
            float4 v = make_float4(0.f, 0.f, 0.f, 0.f);
            if (gr < M) {
                v = *(const float4*)(A + (size_t)gr * K + kb + c4 * 4);
                if (mode == 1) {
                    float4 w = *(const float4*)(A2 + (size_t)gr * K + kb + c4 * 4);
                    v.x += w.x; v.y += w.y; v.z += w.z; v.w += w.w;
                } else if (mode == 2) {
                    int kc = kb + c4 * 4;
                    float4 sc = *(const float4*)(scale + kc);
                    float4 sh = *(const float4*)(shift + kc);
                    v.x = fmaxf(fmaf(v.x, sc.x, sh.x), 0.f);
                    v.y = fmaxf(fmaf(v.y, sc.y, sh.y), 0.f);
                    v.z = fmaxf(fmaf(v.z, sc.z, sh.z), 0.f);
                    v.w = fmaxf(fmaf(v.w, sc.w, sh.w), 0.f);
                }
            }
            As[r][c4 * 4 + 0] = v.x; As[r][c4 * 4 + 1] = v.y;
            As[r][c4 * 4 + 2] = v.z; As[r][c4 * 4 + 3] = v.w;
        }
        // load W tile (32x128) -> 1024 float4, 4 per thread
        #pragma unroll
        for (int i = 0; i < 4; i++) {
            int idx = tid + i * 256;
            int r = idx >> 5, c4 = idx & 31;
            float4 v = *(const float4*)(W + (size_t)(kb + r) * BN + c4 * 4);
            *(float4*)&Bs[r][c4 * 4] = v;
        }
        __syncthreads();

        #pragma unroll
        for (int kk = 0; kk < BK; kk++) {
            float a[4];
            #pragma unroll
            for (int i = 0; i < 4; i++) a[i] = As[ty * 4 + i][kk];
            float4 b0 = *(const float4*)&Bs[kk][tx * 8];
            float4 b1 = *(const float4*)&Bs[kk][tx * 8 + 4];
            #pragma unroll
            for (int i = 0; i < 4; i++) {
                acc[i][0] = fmaf(a[i], b0.x, acc[i][0]);
                acc[i][1] = fmaf(a[i], b0.y, acc[i][1]);
                acc[i][2] = fmaf(a[i], b0.z, acc[i][2]);
                acc[i][3] = fmaf(a[i], b0.w, acc[i][3]);
                acc[i][4] = fmaf(a[i], b1.x, acc[i][4]);
                acc[i][5] = fmaf(a[i], b1.y, acc[i][5]);
                acc[i][6] = fmaf(a[i], b1.z, acc[i][6]);
                acc[i][7] = fmaf(a[i], b1.w, acc[i][7]);
            }
        }
        __syncthreads();
    }

    float4 bv0 = *(const float4*)(bias + tx * 8);
    float4 bv1 = *(const float4*)(bias + tx * 8 + 4);
    #pragma unroll
    for (int i = 0; i < 4; i++) {
        int gr = m0 + ty * 4 + i;
        if (gr < M) {
            float4 o0 = make_float4(acc[i][0] + bv0.x, acc[i][1] + bv0.y,
                                    acc[i][2] + bv0.z, acc[i][3] + bv0.w);
            float4 o1 = make_float4(acc[i][4] + bv1.x, acc[i][5] + bv1.y,
                                    acc[i][6] + bv1.z, acc[i][7] + bv1.w);
            *(float4*)(C + (size_t)gr * BN + tx * 8)     = o0;
            *(float4*)(C + (size_t)gr * BN + tx * 8 + 4) = o1;
        }
    }
}

// ---------------- fused edge kernel: agg[dst] += relu(h[src] + edge_attr @ We + be) ----------------
__global__ __launch_bounds__(256) void edge_kernel(
    const float* __restrict__ h, const float* __restrict__ ea,
    const int* __restrict__ src, const int* __restrict__ dst,
    const float* __restrict__ We, const float* __restrict__ be,
    float* __restrict__ agg, int E)
{
    __shared__ __align__(16) float Ws[16][128];
    __shared__ __align__(16) float bs[128];
    const int tid = threadIdx.x;
    for (int i = tid; i < 16 * 128; i += 256) Ws[i >> 7][i & 127] = We[i];
    if (tid < 128) bs[tid] = be[tid];
    __syncthreads();

    const int warp = tid >> 5, lid = tid & 31;
    const int j0 = lid * 4;

    for (int e = blockIdx.x * 8 + warp; e < E; e += gridDim.x * 8) {
        float v = (lid < 16) ? ea[(size_t)e * 16 + lid] : 0.f;
        int s = src[e], d = dst[e];
        float4 acc = *(const float4*)&bs[j0];
        #pragma unroll
        for (int k = 0; k < 16; k++) {
            float a = __shfl_sync(0xffffffffu, v, k);
            float4 w = *(const float4*)&Ws[k][j0];
            acc.x = fmaf(a, w.x, acc.x);
            acc.y = fmaf(a, w.y, acc.y);
            acc.z = fmaf(a, w.z, acc.z);
            acc.w = fmaf(a, w.w, acc.w);
        }
        float4 hv = *(const float4*)(h + (size_t)s * 128 + j0);
        float mx = fmaxf(acc.x + hv.x, 0.f);
        float my = fmaxf(acc.y + hv.y, 0.f);
        float mz = fmaxf(acc.z + hv.z, 0.f);
        float mw = fmaxf(acc.w + hv.w, 0.f);
        float* p = agg + (size_t)d * 128 + j0;
        asm volatile("red.global.add.v4.f32 [%0], {%1,%2,%3,%4};"
                     :: "l"(p), "f"(mx), "f"(my), "f"(mz), "f"(mw) : "memory");
    }
}

// ---------------- column stats (sum, sumsq) over M rows x 128 cols ----------------
__global__ __launch_bounds__(128) void stats_kernel(
    const float* __restrict__ T, int M,
    float* __restrict__ gsum, float* __restrict__ gsumsq)
{
    const int c = threadIdx.x;
    float s = 0.f, s2 = 0.f;
    for (int r = blockIdx.x; r < M; r += gridDim.x) {
        float v = T[(size_t)r * 128 + c];
        s += v; s2 = fmaf(v, v, s2);
    }
    atomicAdd(&gsum[c], s);
    atomicAdd(&gsumsq[c], s2);
}

__global__ void finalize_bn(const float* __restrict__ gsum, const float* __restrict__ gsumsq,
                            const float* __restrict__ g, const float* __restrict__ b,
                            float invM, float* __restrict__ scale, float* __restrict__ shift)
{
    int c = threadIdx.x;
    float m = gsum[c] * invM;
    float v = gsumsq[c] * invM - m * m;
    float sc = g[c] * rsqrtf(v + 1e-5f);
    scale[c] = sc;
    shift[c] = b[c] - m * sc;
}

__global__ void bn_relu_apply(const float* __restrict__ T, const float* __restrict__ scale,
                              const float* __restrict__ shift, float* __restrict__ outl, size_t total)
{
    size_t i = (size_t)blockIdx.x * blockDim.x + threadIdx.x;
    if (i < total) {
        int c = (int)(i & 127);
        outl[i] = fmaxf(fmaf(T[i], scale[c], shift[c]), 0.f);
    }
}

// ---------------- pooling: mean + max per graph (batch is sorted) ----------------
__device__ __forceinline__ int lower_bound_i(const int* a, int n, int key) {
    int lo = 0, hi = n;
    while (lo < hi) { int mid = (lo + hi) >> 1; if (a[mid] < key) lo = mid + 1; else hi = mid; }
    return lo;
}

__global__ __launch_bounds__(384) void pool_kernel(
    const float* __restrict__ o0, const float* __restrict__ o1, const float* __restrict__ o2,
    const int* __restrict__ batch, int Nn, float* __restrict__ zcat)
{
    const int g = blockIdx.x;
    const int lo = lower_bound_i(batch, Nn, g);
    const int hi = lower_bound_i(batch, Nn, g + 1);
    const int c = threadIdx.x;                     // 0..383
    const float* src = (c < 128) ? o0 : ((c < 256) ? o1 : o2);
    const int cc = c & 127;
    float s = 0.f, mx = 0.f;                       // relu outputs are >= 0
    for (int n = lo; n < hi; n++) {
        float v = src[(size_t)n * 128 + cc];
        s += v; mx = fmaxf(mx, v);
    }
    int cnt = hi - lo;
    float mean = s / (float)(cnt > 0 ? cnt : 1);
    zcat[(size_t)g * 768 + c]       = mean;
    zcat[(size_t)g * 768 + 384 + c] = mx;
}

// ---------------- head ----------------
__global__ __launch_bounds__(128) void head1_kernel(
    const float* __restrict__ zcat, const float* __restrict__ W1,
    const float* __restrict__ b1, float* __restrict__ zh)
{
    __shared__ __align__(16) float zs[768];
    const int g = blockIdx.x;
    for (int k = threadIdx.x; k < 768; k += 128) zs[k] = zcat[(size_t)g * 768 + k];
    __syncthreads();
    const int j = threadIdx.x;
    float acc = b1[j];
    #pragma unroll 8
    for (int k = 0; k < 768; k++) acc = fmaf(zs[k], W1[(size_t)k * 128 + j], acc);
    zh[(size_t)g * 128 + j] = acc;
}

__global__ __launch_bounds__(128) void head_stats_kernel(
    const float* __restrict__ zh, const float* __restrict__ g, const float* __restrict__ b,
    int G, float* __restrict__ scale, float* __restrict__ shift)
{
    int c = threadIdx.x;
    float s = 0.f, s2 = 0.f;
    for (int r = 0; r < G; r++) { float v = zh[(size_t)r * 128 + c]; s += v; s2 = fmaf(v, v, s2); }
    float invG = 1.f / (float)G;
    float m = s * invG;
    float var = s2 * invG - m * m;
    float sc = g[c] * rsqrtf(var + 1e-5f);
    scale[c] = sc;
    shift[c] = b[c] - m * sc;
}

__global__ __launch_bounds__(128) void head2_kernel(
    const float* __restrict__ zh, const float* __restrict__ scale, const float* __restrict__ shift,
    const float* __restrict__ W2, const float* __restrict__ b2, float* __restrict__ out)
{
    __shared__ float red[128];
    const int g = blockIdx.x, j = threadIdx.x;
    float v = fmaxf(fmaf(zh[(size_t)g * 128 + j], scale[j], shift[j]), 0.f) * W2[j];
    red[j] = v;
    __syncthreads();
    #pragma unroll
    for (int s = 64; s > 0; s >>= 1) {
        if (j < s) red[j] += red[j + s];
        __syncthreads();
    }
    if (j == 0) out[g] = red[0] + b2[0];
}

// ---------------- launcher ----------------
extern "C" void kernel_launch(void* const* d_in, const int* in_sizes, int n_in,
                              void* d_out, int out_size)
{
    const float* x         = (const float*)d_in[0];
    const float* edge_attr = (const float*)d_in[1];
    const int*   src       = (const int*)  d_in[2];
    const int*   dst       = (const int*)  d_in[3];
    const int*   batch     = (const int*)  d_in[4];
    const float* Wp        = (const float*)d_in[5];
    const float* bp        = (const float*)d_in[6];
    const float* conv_We   = (const float*)d_in[7];
    const float* conv_be   = (const float*)d_in[8];
    const float* conv_W1   = (const float*)d_in[9];
    const float* conv_b1   = (const float*)d_in[10];
    const float* conv_g1   = (const float*)d_in[11];
    const float* conv_bt1  = (const float*)d_in[12];
    const float* conv_W2   = (const float*)d_in[13];
    const float* conv_b2   = (const float*)d_in[14];
    const float* bn_g      = (const float*)d_in[15];
    const float* bn_b      = (const float*)d_in[16];
    const float* head_W1   = (const float*)d_in[17];
    const float* head_b1   = (const float*)d_in[18];
    const float* head_g    = (const float*)d_in[19];
    const float* head_bt   = (const float*)d_in[20];
    const float* head_W2   = (const float*)d_in[21];
    const float* head_b2   = (const float*)d_in[22];

    const int Nn = in_sizes[0] / 64;     // 50000
    const int E  = in_sizes[2];          // 800000
    const int G  = out_size;             // 256

    float *hp, *agg, *t, *outl, *zcat, *zh, *stats, *scale, *shift;
    cudaGetSymbolAddress((void**)&hp,    d_hp);
    cudaGetSymbolAddress((void**)&agg,   d_agg);
    cudaGetSymbolAddress((void**)&t,     d_t);
    cudaGetSymbolAddress((void**)&outl,  d_outl);
    cudaGetSymbolAddress((void**)&zcat,  d_zcat);
    cudaGetSymbolAddress((void**)&zh,    d_zh);
    cudaGetSymbolAddress((void**)&stats, d_stats);
    cudaGetSymbolAddress((void**)&scale, d_scale);
    cudaGetSymbolAddress((void**)&shift, d_shift);

    const int gB = (Nn + 63) / 64;
    const float invM = 1.f / (float)Nn;
    const size_t nodeBytes = (size_t)Nn * 128 * sizeof(float);

    // projection: h = x @ Wp + bp
    gemm_kernel<<<gB, 256>>>(x, nullptr, nullptr, nullptr, Wp, bp, hp, Nn, 64, 0);

    const float* h = hp;
    for (int l = 0; l < 3; l++) {
        const float* We_l = conv_We + (size_t)l * 16 * 128;
        const float* be_l = conv_be + (size_t)l * 128;
        const float* W1_l = conv_W1 + (size_t)l * 128 * 128;
        const float* b1_l = conv_b1 + (size_t)l * 128;
        const float* g1_l = conv_g1 + (size_t)l * 128;
        const float* t1_l = conv_bt1 + (size_t)l * 128;
        const float* W2_l = conv_W2 + (size_t)l * 128 * 128;
        const float* b2_l = conv_b2 + (size_t)l * 128;
        const float* bg_l = bn_g + (size_t)l * 128;
        const float* bb_l = bn_b + (size_t)l * 128;
        float* outl_l = outl + (size_t)l * Nn * 128;

        cudaMemsetAsync(agg, 0, nodeBytes, 0);
        edge_kernel<<<2048, 256>>>(h, edge_attr, src, dst, We_l, be_l, agg, E);

        // t1 = (h + agg) @ W1 + b1
        gemm_kernel<<<gB, 256>>>(h, agg, nullptr, nullptr, W1_l, b1_l, t, Nn, 128, 1);

        cudaMemsetAsync(stats, 0, 256 * sizeof(float), 0);
        stats_kernel<<<512, 128>>>(t, Nn, stats, stats + 128);
        finalize_bn<<<1, 128>>>(stats, stats + 128, g1_l, t1_l, invM, scale, shift);

        // t2 = relu(bn(t1)) @ W2 + b2   (in-place safe: C row depends only on same A rows)
        gemm_kernel<<<gB, 256>>>(t, nullptr, scale, shift, W2_l, b2_l, t, Nn, 128, 2);

        cudaMemsetAsync(stats, 0, 256 * sizeof(float), 0);
        stats_kernel<<<512, 128>>>(t, Nn, stats, stats + 128);
        finalize_bn<<<1, 128>>>(stats, stats + 128, bg_l, bb_l, invM, scale, shift);

        bn_relu_apply<<<(int)(((size_t)Nn * 128 + 255) / 256), 256>>>(t, scale, shift, outl_l,
                                                                      (size_t)Nn * 128);
        h = outl_l;
    }

    pool_kernel<<<G, 384>>>(outl, outl + (size_t)Nn * 128, outl + (size_t)2 * Nn * 128,
                            batch, Nn, zcat);
    head1_kernel<<<G, 128>>>(zcat, head_W1, head_b1, zh);
    head_stats_kernel<<<1, 128>>>(zh, head_g, head_bt, G, scale, shift);
    head2_kernel<<<G, 128>>>(zh, scale, shift, head_W2, head_b2, (float*)d_out);
}

// round 5
// speedup vs baseline: 1.2281x; 1.2281x over previous
#include <cuda_runtime.h>
#include <cuda_bf16.h>
#include <cstdint>

#define MAX_N 50000
#define HIDN 128

// ---------------- scratch (no allocations allowed) ----------------
__device__ float d_hp  [(size_t)MAX_N * HIDN];
__device__ float d_agg [(size_t)MAX_N * HIDN];
__device__ float d_t   [(size_t)MAX_N * HIDN];
__device__ float d_outl[(size_t)3 * MAX_N * HIDN];
__device__ float d_zcat[256 * 768];
__device__ float d_zh  [256 * 128];
__device__ float d_stats[6 * 256];   // 3 layers x 2 BN x (sum[128], sumsq[128])
__device__ float d_hsc[256];         // head scale/shift

// =================================================================
// GEMM: C[M x 128] = f(A[M x K]) @ W[K x 128] + bias
//   f = identity            if gstats_in == nullptr
//   f = relu(bn(A))         if gstats_in != nullptr (scale/shift from raw stats)
// optional: C2 gets a copy of C; gstats_out accumulates column sum/sumsq of C.
// BM=128, BN=128, BK=16, 256 threads, 8x8 per-thread tile.
// =================================================================
__global__ __launch_bounds__(256) void gemm_kernel(
    const float* __restrict__ A, const float* __restrict__ W,
    const float* __restrict__ bias,
    const float* __restrict__ gstats_in, const float* __restrict__ gamma,
    const float* __restrict__ beta, float invM,
    float* __restrict__ C, float* __restrict__ C2,
    float* __restrict__ gstats_out, int M, int K)
{
    constexpr int BM = 128, BN = 128, BK = 16;
    __shared__ __align__(16) float As[BK][BM + 4];   // stride 132 (16B aligned)
    __shared__ __align__(16) float Bs[BK][BN];
    __shared__ float sSc[128];
    __shared__ float sSh[128];

    const int tid = threadIdx.x;
    const int m0 = blockIdx.x * BM;
    const int tx = tid & 15;     // 16 col groups of 8
    const int ty = tid >> 4;     // 16 row groups of 8

    if (gstats_in && tid < 128) {
        float m = gstats_in[tid] * invM;
        float v = gstats_in[128 + tid] * invM - m * m;
        float sc = gamma[tid] * rsqrtf(v + 1e-5f);
        sSc[tid] = sc;
        sSh[tid] = beta[tid] - m * sc;
    }
    __syncthreads();

    float acc[8][8];
    #pragma unroll
    for (int i = 0; i < 8; i++)
        #pragma unroll
        for (int j = 0; j < 8; j++) acc[i][j] = 0.f;

    for (int kb = 0; kb < K; kb += BK) {
        // ---- A tile: 128 x 16 (transposed store) ----
        #pragma unroll
        for (int i = 0; i < 2; i++) {
            int idx = tid + i * 256;
            int r = idx >> 2, c4 = idx & 3;
            int gr = m0 + r;
            float4 v = make_float4(0.f, 0.f, 0.f, 0.f);
            if (gr < M) {
                v = *(const float4*)(A + (size_t)gr * K + kb + c4 * 4);
                if (gstats_in) {
                    int kc = kb + c4 * 4;   // K==128 in bn mode
                    float4 sc = *(const float4*)&sSc[kc];
                    float4 sh = *(const float4*)&sSh[kc];
                    v.x = fmaxf(fmaf(v.x, sc.x, sh.x), 0.f);
                    v.y = fmaxf(fmaf(v.y, sc.y, sh.y), 0.f);
                    v.z = fmaxf(fmaf(v.z, sc.z, sh.z), 0.f);
                    v.w = fmaxf(fmaf(v.w, sc.w, sh.w), 0.f);
                }
            }
            As[c4 * 4 + 0][r] = v.x;
            As[c4 * 4 + 1][r] = v.y;
            As[c4 * 4 + 2][r] = v.z;
            As[c4 * 4 + 3][r] = v.w;
        }
        // ---- B tile: 16 x 128 ----
        #pragma unroll
        for (int i = 0; i < 2; i++) {
            int idx = tid + i * 256;
            int r = idx >> 5, c4 = idx & 31;
            *(float4*)&Bs[r][c4 * 4] =
                *(const float4*)(W + (size_t)(kb + r) * BN + c4 * 4);
        }
        __syncthreads();

        #pragma unroll
        for (int kk = 0; kk < BK; kk++) {
            float4 a0 = *(const float4*)&As[kk][ty * 8];
            float4 a1 = *(const float4*)&As[kk][ty * 8 + 4];
            float4 b0 = *(const float4*)&Bs[kk][tx * 8];
            float4 b1 = *(const float4*)&Bs[kk][tx * 8 + 4];
            float av[8] = {a0.x, a0.y, a0.z, a0.w, a1.x, a1.y, a1.z, a1.w};
            float bv[8] = {b0.x, b0.y, b0.z, b0.w, b1.x, b1.y, b1.z, b1.w};
            #pragma unroll
            for (int i = 0; i < 8; i++)
                #pragma unroll
                for (int j = 0; j < 8; j++)
                    acc[i][j] = fmaf(av[i], bv[j], acc[i][j]);
        }
        __syncthreads();
    }

    float4 bv0 = *(const float4*)(bias + tx * 8);
    float4 bv1 = *(const float4*)(bias + tx * 8 + 4);
    float bb[8] = {bv0.x, bv0.y, bv0.z, bv0.w, bv1.x, bv1.y, bv1.z, bv1.w};

    float psum[8], psq[8];
    #pragma unroll
    for (int j = 0; j < 8; j++) { psum[j] = 0.f; psq[j] = 0.f; }

    #pragma unroll
    for (int i = 0; i < 8; i++) {
        int gr = m0 + ty * 8 + i;
        if (gr < M) {
            #pragma unroll
            for (int j = 0; j < 8; j++) {
                float v = acc[i][j] + bb[j];
                acc[i][j] = v;
                psum[j] += v;
                psq[j] = fmaf(v, v, psq[j]);
            }
            float4 o0 = make_float4(acc[i][0], acc[i][1], acc[i][2], acc[i][3]);
            float4 o1 = make_float4(acc[i][4], acc[i][5], acc[i][6], acc[i][7]);
            *(float4*)(C + (size_t)gr * BN + tx * 8)     = o0;
            *(float4*)(C + (size_t)gr * BN + tx * 8 + 4) = o1;
            if (C2) {
                *(float4*)(C2 + (size_t)gr * BN + tx * 8)     = o0;
                *(float4*)(C2 + (size_t)gr * BN + tx * 8 + 4) = o1;
            }
        }
    }

    if (gstats_out) {
        __syncthreads();
        float* rs = &As[0][0];     // 16*132 >= 2048
        float* rq = &Bs[0][0];     // 16*128 = 2048
        #pragma unroll
        for (int j = 0; j < 8; j++) {
            rs[ty * 128 + tx * 8 + j] = psum[j];
            rq[ty * 128 + tx * 8 + j] = psq[j];
        }
        __syncthreads();
        if (tid < 128) {
            float s = 0.f, q = 0.f;
            #pragma unroll
            for (int t = 0; t < 16; t++) {
                s += rs[t * 128 + tid];
                q += rq[t * 128 + tid];
            }
            atomicAdd(&gstats_out[tid], s);
            atomicAdd(&gstats_out[128 + tid], q);
        }
    }
}

// ---------------- fused edge kernel: agg[dst] += relu(h[src] + edge_attr @ We + be) ----------------
// (agg is pre-initialized with h, so after this agg = h + sum(msg))
__global__ __launch_bounds__(256) void edge_kernel(
    const float* __restrict__ h, const float* __restrict__ ea,
    const int* __restrict__ src, const int* __restrict__ dst,
    const float* __restrict__ We, const float* __restrict__ be,
    float* __restrict__ agg, int E)
{
    __shared__ __align__(16) float Ws[16][128];
    __shared__ __align__(16) float bs[128];
    const int tid = threadIdx.x;
    for (int i = tid; i < 16 * 128; i += 256) Ws[i >> 7][i & 127] = We[i];
    if (tid < 128) bs[tid] = be[tid];
    __syncthreads();

    const int warp = tid >> 5, lid = tid & 31;
    const int j0 = lid * 4;

    for (int e = blockIdx.x * 8 + warp; e < E; e += gridDim.x * 8) {
        float v = (lid < 16) ? ea[(size_t)e * 16 + lid] : 0.f;
        int s = src[e], d = dst[e];
        float4 acc = *(const float4*)&bs[j0];
        #pragma unroll
        for (int k = 0; k < 16; k++) {
            float a = __shfl_sync(0xffffffffu, v, k);
            float4 w = *(const float4*)&Ws[k][j0];
            acc.x = fmaf(a, w.x, acc.x);
            acc.y = fmaf(a, w.y, acc.y);
            acc.z = fmaf(a, w.z, acc.z);
            acc.w = fmaf(a, w.w, acc.w);
        }
        float4 hv = *(const float4*)(h + (size_t)s * 128 + j0);
        float mx = fmaxf(acc.x + hv.x, 0.f);
        float my = fmaxf(acc.y + hv.y, 0.f);
        float mz = fmaxf(acc.z + hv.z, 0.f);
        float mw = fmaxf(acc.w + hv.w, 0.f);
        float* p = agg + (size_t)d * 128 + j0;
        asm volatile("red.global.add.v4.f32 [%0], {%1,%2,%3,%4};"
                     :: "l"(p), "f"(mx), "f"(my), "f"(mz), "f"(mw) : "memory");
    }
}

// ---------------- bn+relu apply: outl = relu(bn(T)); optionally agg = outl (init for next layer) ----------------
__global__ __launch_bounds__(256) void bn_apply_kernel(
    const float* __restrict__ T, const float* __restrict__ gstats,
    const float* __restrict__ gamma, const float* __restrict__ beta, float invM,
    float* __restrict__ outl, float* __restrict__ aggcopy, int total4)
{
    __shared__ float sSc[128];
    __shared__ float sSh[128];
    if (threadIdx.x < 128) {
        int c = threadIdx.x;
        float m = gstats[c] * invM;
        float v = gstats[128 + c] * invM - m * m;
        float sc = gamma[c] * rsqrtf(v + 1e-5f);
        sSc[c] = sc;
        sSh[c] = beta[c] - m * sc;
    }
    __syncthreads();
    int i = blockIdx.x * blockDim.x + threadIdx.x;
    if (i < total4) {
        int c4 = (i & 31) * 4;
        float4 v = *(const float4*)(T + (size_t)i * 4);
        float4 sc = *(const float4*)&sSc[c4];
        float4 sh = *(const float4*)&sSh[c4];
        float4 r;
        r.x = fmaxf(fmaf(v.x, sc.x, sh.x), 0.f);
        r.y = fmaxf(fmaf(v.y, sc.y, sh.y), 0.f);
        r.z = fmaxf(fmaf(v.z, sc.z, sh.z), 0.f);
        r.w = fmaxf(fmaf(v.w, sc.w, sh.w), 0.f);
        *(float4*)(outl + (size_t)i * 4) = r;
        if (aggcopy) *(float4*)(aggcopy + (size_t)i * 4) = r;
    }
}

// ---------------- pooling: mean + max per graph (batch is sorted) ----------------
__device__ __forceinline__ int lower_bound_i(const int* a, int n, int key) {
    int lo = 0, hi = n;
    while (lo < hi) { int mid = (lo + hi) >> 1; if (a[mid] < key) lo = mid + 1; else hi = mid; }
    return lo;
}

__global__ __launch_bounds__(384) void pool_kernel(
    const float* __restrict__ o0, const float* __restrict__ o1, const float* __restrict__ o2,
    const int* __restrict__ batch, int Nn, float* __restrict__ zcat)
{
    const int g = blockIdx.x;
    const int lo = lower_bound_i(batch, Nn, g);
    const int hi = lower_bound_i(batch, Nn, g + 1);
    const int c = threadIdx.x;                     // 0..383
    const float* src = (c < 128) ? o0 : ((c < 256) ? o1 : o2);
    const int cc = c & 127;
    float s = 0.f, mx = 0.f;                       // relu outputs are >= 0
    for (int n = lo; n < hi; n++) {
        float v = src[(size_t)n * 128 + cc];
        s += v; mx = fmaxf(mx, v);
    }
    int cnt = hi - lo;
    float mean = s / (float)(cnt > 0 ? cnt : 1);
    zcat[(size_t)g * 768 + c]       = mean;
    zcat[(size_t)g * 768 + 384 + c] = mx;
}

// ---------------- head ----------------
__global__ __launch_bounds__(128) void head1_kernel(
    const float* __restrict__ zcat, const float* __restrict__ W1,
    const float* __restrict__ b1, float* __restrict__ zh)
{
    __shared__ __align__(16) float zs[768];
    const int g = blockIdx.x;
    for (int k = threadIdx.x; k < 768; k += 128) zs[k] = zcat[(size_t)g * 768 + k];
    __syncthreads();
    const int j = threadIdx.x;
    float acc = b1[j];
    #pragma unroll 8
    for (int k = 0; k < 768; k++) acc = fmaf(zs[k], W1[(size_t)k * 128 + j], acc);
    zh[(size_t)g * 128 + j] = acc;
}

__global__ __launch_bounds__(128) void head_stats_kernel(
    const float* __restrict__ zh, const float* __restrict__ g, const float* __restrict__ b,
    int G, float* __restrict__ sc_sh)
{
    int c = threadIdx.x;
    float s = 0.f, s2 = 0.f;
    for (int r = 0; r < G; r++) { float v = zh[(size_t)r * 128 + c]; s += v; s2 = fmaf(v, v, s2); }
    float invG = 1.f / (float)G;
    float m = s * invG;
    float var = s2 * invG - m * m;
    float sc = g[c] * rsqrtf(var + 1e-5f);
    sc_sh[c] = sc;
    sc_sh[128 + c] = b[c] - m * sc;
}

__global__ __launch_bounds__(128) void head2_kernel(
    const float* __restrict__ zh, const float* __restrict__ sc_sh,
    const float* __restrict__ W2, const float* __restrict__ b2, float* __restrict__ out)
{
    __shared__ float red[128];
    const int g = blockIdx.x, j = threadIdx.x;
    float v = fmaxf(fmaf(zh[(size_t)g * 128 + j], sc_sh[j], sc_sh[128 + j]), 0.f) * W2[j];
    red[j] = v;
    __syncthreads();
    #pragma unroll
    for (int s = 64; s > 0; s >>= 1) {
        if (j < s) red[j] += red[j + s];
        __syncthreads();
    }
    if (j == 0) out[g] = red[0] + b2[0];
}

// ---------------- launcher ----------------
extern "C" void kernel_launch(void* const* d_in, const int* in_sizes, int n_in,
                              void* d_out, int out_size)
{
    const float* x         = (const float*)d_in[0];
    const float* edge_attr = (const float*)d_in[1];
    const int*   src       = (const int*)  d_in[2];
    const int*   dst       = (const int*)  d_in[3];
    const int*   batch     = (const int*)  d_in[4];
    const float* Wp        = (const float*)d_in[5];
    const float* bp        = (const float*)d_in[6];
    const float* conv_We   = (const float*)d_in[7];
    const float* conv_be   = (const float*)d_in[8];
    const float* conv_W1   = (const float*)d_in[9];
    const float* conv_b1   = (const float*)d_in[10];
    const float* conv_g1   = (const float*)d_in[11];
    const float* conv_bt1  = (const float*)d_in[12];
    const float* conv_W2   = (const float*)d_in[13];
    const float* conv_b2   = (const float*)d_in[14];
    const float* bn_g      = (const float*)d_in[15];
    const float* bn_b      = (const float*)d_in[16];
    const float* head_W1   = (const float*)d_in[17];
    const float* head_b1   = (const float*)d_in[18];
    const float* head_g    = (const float*)d_in[19];
    const float* head_bt   = (const float*)d_in[20];
    const float* head_W2   = (const float*)d_in[21];
    const float* head_b2   = (const float*)d_in[22];

    const int Nn = in_sizes[0] / 64;     // 50000
    const int E  = in_sizes[2];          // 800000
    const int G  = out_size;             // 256

    float *hp, *agg, *t, *outl, *zcat, *zh, *stats, *hsc;
    cudaGetSymbolAddress((void**)&hp,    d_hp);
    cudaGetSymbolAddress((void**)&agg,   d_agg);
    cudaGetSymbolAddress((void**)&t,     d_t);
    cudaGetSymbolAddress((void**)&outl,  d_outl);
    cudaGetSymbolAddress((void**)&zcat,  d_zcat);
    cudaGetSymbolAddress((void**)&zh,    d_zh);
    cudaGetSymbolAddress((void**)&stats, d_stats);
    cudaGetSymbolAddress((void**)&hsc,   d_hsc);

    const int gB = (Nn + 127) / 128;
    const float invM = 1.f / (float)Nn;
    const int total4 = Nn * 32;          // N*128/4

    // zero all BN stat accumulators (re-zeroed at the start of every launch,
    // so the graph is replay-safe)
    cudaMemsetAsync(stats, 0, 6 * 256 * sizeof(float), 0);

    // projection: h = x @ Wp + bp ; also agg = h
    gemm_kernel<<<gB, 256>>>(x, Wp, bp, nullptr, nullptr, nullptr, 0.f,
                             hp, agg, nullptr, Nn, 64);

    const float* h = hp;
    for (int l = 0; l < 3; l++) {
        const float* We_l = conv_We + (size_t)l * 16 * 128;
        const float* be_l = conv_be + (size_t)l * 128;
        const float* W1_l = conv_W1 + (size_t)l * 128 * 128;
        const float* b1_l = conv_b1 + (size_t)l * 128;
        const float* g1_l = conv_g1 + (size_t)l * 128;
        const float* t1_l = conv_bt1 + (size_t)l * 128;
        const float* W2_l = conv_W2 + (size_t)l * 128 * 128;
        const float* b2_l = conv_b2 + (size_t)l * 128;
        const float* bg_l = bn_g + (size_t)l * 128;
        const float* bb_l = bn_b + (size_t)l * 128;
        float* outl_l = outl + (size_t)l * Nn * 128;
        float* S0 = stats + (size_t)(2 * l) * 256;
        float* S1 = stats + (size_t)(2 * l + 1) * 256;

        // agg (== h + sum msg after this) via atomic reductions
        edge_kernel<<<4096, 256>>>(h, edge_attr, src, dst, We_l, be_l, agg, E);

        // t1 = agg @ W1 + b1 ; accumulate col stats of t1 into S0
        gemm_kernel<<<gB, 256>>>(agg, W1_l, b1_l, nullptr, nullptr, nullptr, 0.f,
                                 t, nullptr, S0, Nn, 128);

        // t2 = relu(bn_{S0}(t1)) @ W2 + b2 (in place) ; stats of t2 into S1
        gemm_kernel<<<gB, 256>>>(t, W2_l, b2_l, S0, g1_l, t1_l, invM,
                                 t, nullptr, S1, Nn, 128);

        // out_l = relu(bn_{S1}(t2)) ; also agg = out_l for next layer
        bn_apply_kernel<<<(total4 + 255) / 256, 256>>>(
            t, S1, bg_l, bb_l, invM, outl_l, (l < 2) ? agg : nullptr, total4);

        h = outl_l;
    }

    pool_kernel<<<G, 384>>>(outl, outl + (size_t)Nn * 128, outl + (size_t)2 * Nn * 128,
                            batch, Nn, zcat);
    head1_kernel<<<G, 128>>>(zcat, head_W1, head_b1, zh);
    head_stats_kernel<<<1, 128>>>(zh, head_g, head_bt, G, hsc);
    head2_kernel<<<G, 128>>>(zh, hsc, head_W2, head_b2, (float*)d_out);
}

// round 10
// speedup vs baseline: 1.4205x; 1.1567x over previous
#include <cuda_runtime.h>
#include <cuda_bf16.h>
#include <cstdint>

#define MAX_N 50000
#define HIDN 128

// ---------------- scratch (no allocations allowed) ----------------
__device__ float d_hp  [(size_t)MAX_N * HIDN];
__device__ float d_agg [(size_t)MAX_N * HIDN];
__device__ float d_t   [(size_t)MAX_N * HIDN];
__device__ float d_outl[(size_t)3 * MAX_N * HIDN];
__device__ float d_zcat[256 * 768];
__device__ float d_zh  [256 * 128];
__device__ float d_stats[6 * 256];   // 3 layers x 2 BN x (sum[128], sumsq[128])
__device__ float d_hsc[256];         // head scale/shift
__device__ __nv_bfloat16 d_whi[128 * 128];   // W split hi, [n][k] layout
__device__ __nv_bfloat16 d_wlo[128 * 128];   // W split lo, [n][k] layout

// ================= helpers =================
__device__ __forceinline__ uint32_t smem_to_u32(const void* smem_ptr) {
    uint32_t addr;
    asm("{ .reg .u64 tmp; cvta.to.shared.u64 tmp, %1; cvt.u32.u64 %0, tmp; }"
        : "=r"(addr) : "l"(smem_ptr));
    return addr;
}

__device__ __forceinline__ void ldsm4(uint32_t* r, uint32_t addr) {
    asm volatile("ldmatrix.sync.aligned.m8n8.x4.shared.b16 {%0,%1,%2,%3}, [%4];"
                 : "=r"(r[0]), "=r"(r[1]), "=r"(r[2]), "=r"(r[3]) : "r"(addr));
}

__device__ __forceinline__ void mma16816(float* d, const uint32_t* a, const uint32_t* b) {
    asm volatile(
        "mma.sync.aligned.m16n8k16.row.col.f32.bf16.bf16.f32 "
        "{%0,%1,%2,%3}, {%4,%5,%6,%7}, {%8,%9}, {%0,%1,%2,%3};"
        : "+f"(d[0]), "+f"(d[1]), "+f"(d[2]), "+f"(d[3])
        : "r"(a[0]), "r"(a[1]), "r"(a[2]), "r"(a[3]), "r"(b[0]), "r"(b[1]));
}

__device__ __forceinline__ uint32_t pack2(float a, float b) {
    __nv_bfloat162 t = __floats2bfloat162_rn(a, b);   // .x = a (low half)
    return *(uint32_t*)&t;
}

// ---------------- W split: W[k][n] fp32 -> Whi/Wlo[n][k] bf16 ----------------
__global__ __launch_bounds__(256) void conv_w(
    const float* __restrict__ W,
    __nv_bfloat16* __restrict__ Whi, __nv_bfloat16* __restrict__ Wlo)
{
    for (int i = blockIdx.x * 256 + threadIdx.x; i < 128 * 128; i += gridDim.x * 256) {
        int k = i >> 7, n = i & 127;
        float v = W[i];
        __nv_bfloat16 h = __float2bfloat16(v);
        float lo = v - __bfloat162float(h);
        Whi[n * 128 + k] = h;
        Wlo[n * 128 + k] = __float2bfloat16(lo);
    }
}

// =================================================================
// HMMA GEMM: C[M x 128] = f(A[M x 128]) @ W[128 x 128] + bias
//   f = identity if gstats==nullptr, else relu(bn(A))
// fp32 emulated as bf16 split: Ahi*Bhi + Alo*Bhi + Ahi*Blo
// 256 threads (8 warps, 4x2), warp tile 32x64, mma.m16n8k16.bf16.
// SMEM rows stride 40 bf16 (80B) -> conflict-free ldmatrix.
// =================================================================
__global__ __launch_bounds__(256, 2) void mma_gemm(
    const float* __restrict__ A,
    const __nv_bfloat16* __restrict__ Whi, const __nv_bfloat16* __restrict__ Wlo,
    const float* __restrict__ bias,
    const float* __restrict__ gstats, const float* __restrict__ gamma,
    const float* __restrict__ beta, float invM,
    float* __restrict__ C, int M)
{
    __shared__ __align__(16) __nv_bfloat16 sAhi[128 * 40];
    __shared__ __align__(16) __nv_bfloat16 sAlo[128 * 40];
    __shared__ __align__(16) __nv_bfloat16 sBhi[128 * 40];
    __shared__ __align__(16) __nv_bfloat16 sBlo[128 * 40];
    __shared__ float sBias[128];
    __shared__ float sSc[128];
    __shared__ float sSh[128];

    const int tid = threadIdx.x;
    const int wid = tid >> 5, lane = tid & 31;
    const int wm = wid & 3, wn = wid >> 2;      // 4 (M) x 2 (N) warps
    const int m0 = blockIdx.x * 128;
    const bool dobn = (gstats != nullptr);

    if (tid < 128) {
        sBias[tid] = bias[tid];
        if (dobn) {
            float m = gstats[tid] * invM;
            float v = gstats[128 + tid] * invM - m * m;
            float sc = gamma[tid] * rsqrtf(v + 1e-5f);
            sSc[tid] = sc;
            sSh[tid] = beta[tid] - m * sc;
        }
    }
    __syncthreads();

    float acc[2][8][4];
    #pragma unroll
    for (int i = 0; i < 2; i++)
        #pragma unroll
        for (int j = 0; j < 8; j++)
            #pragma unroll
            for (int q = 0; q < 4; q++) acc[i][j][q] = 0.f;

    const uint32_t aHiB = smem_to_u32(sAhi), aLoB = smem_to_u32(sAlo);
    const uint32_t bHiB = smem_to_u32(sBhi), bLoB = smem_to_u32(sBlo);

    // ldmatrix base offsets (bytes), per lane
    const uint32_t aoffL = (uint32_t)(((wm * 32 + (lane & 15)) * 40 + ((lane >> 4) << 3)) * 2);
    const uint32_t boffL = (uint32_t)(((wn * 64 + ((lane >> 4) << 3) + (lane & 7)) * 40
                                      + (((lane >> 3) & 1) << 3)) * 2);

    for (int kc = 0; kc < 128; kc += 32) {
        if (kc) __syncthreads();               // protect smem reuse

        // ---- A chunk: 128 rows x 32 cols fp32 -> bf16 hi/lo ----
        #pragma unroll
        for (int i = 0; i < 4; i++) {
            int linear = tid + i * 256;        // 0..1023 float4s
            int r = linear >> 3;
            int c4 = (linear & 7) * 4;         // 0..28 within chunk
            int gr = m0 + r;
            float4 v = make_float4(0.f, 0.f, 0.f, 0.f);
            if (gr < M) {
                v = *(const float4*)(A + (size_t)gr * 128 + kc + c4);
                if (dobn) {
                    int kcc = kc + c4;
                    float4 sc = *(const float4*)&sSc[kcc];
                    float4 sh = *(const float4*)&sSh[kcc];
                    v.x = fmaxf(fmaf(v.x, sc.x, sh.x), 0.f);
                    v.y = fmaxf(fmaf(v.y, sc.y, sh.y), 0.f);
                    v.z = fmaxf(fmaf(v.z, sc.z, sh.z), 0.f);
                    v.w = fmaxf(fmaf(v.w, sc.w, sh.w), 0.f);
                }
            }
            __nv_bfloat16 hx = __float2bfloat16(v.x), hy = __float2bfloat16(v.y);
            __nv_bfloat16 hz = __float2bfloat16(v.z), hw = __float2bfloat16(v.w);
            float lx = v.x - __bfloat162float(hx), ly = v.y - __bfloat162float(hy);
            float lz = v.z - __bfloat162float(hz), lw = v.w - __bfloat162float(hw);
            int base = r * 40 + c4;
            __nv_bfloat162 h0; h0.x = hx; h0.y = hy;
            __nv_bfloat162 h1; h1.x = hz; h1.y = hw;
            *(uint32_t*)&sAhi[base]     = *(uint32_t*)&h0;
            *(uint32_t*)&sAhi[base + 2] = *(uint32_t*)&h1;
            *(uint32_t*)&sAlo[base]     = pack2(lx, ly);
            *(uint32_t*)&sAlo[base + 2] = pack2(lz, lw);
        }

        // ---- B chunk: copy pre-split [n][k] bf16, 128 rows x 32 k ----
        #pragma unroll
        for (int i = 0; i < 2; i++) {
            int linear = tid + i * 256;        // 0..511 uint4s
            int r = linear >> 2;
            int c8 = (linear & 3) * 8;
            *(uint4*)&sBhi[r * 40 + c8] = *(const uint4*)(Whi + (size_t)r * 128 + kc + c8);
            *(uint4*)&sBlo[r * 40 + c8] = *(const uint4*)(Wlo + (size_t)r * 128 + kc + c8);
        }
        __syncthreads();

        // ---- 2 k16-steps per chunk ----
        #pragma unroll
        for (int ks = 0; ks < 2; ks++) {
            const uint32_t ko = (uint32_t)(ks * 16 * 2);
            uint32_t ahi[8], alo[8], bf[16];
            ldsm4(ahi,     aHiB + aoffL + ko);
            ldsm4(ahi + 4, aHiB + aoffL + ko + 16 * 40 * 2);
            ldsm4(alo,     aLoB + aoffL + ko);
            ldsm4(alo + 4, aLoB + aoffL + ko + 16 * 40 * 2);
            ldsm4(bf,      bHiB + boffL + ko);
            ldsm4(bf + 4,  bHiB + boffL + ko + 16 * 40 * 2);
            ldsm4(bf + 8,  bHiB + boffL + ko + 32 * 40 * 2);
            ldsm4(bf + 12, bHiB + boffL + ko + 48 * 40 * 2);
            #pragma unroll
            for (int mt = 0; mt < 2; mt++)
                #pragma unroll
                for (int nt = 0; nt < 8; nt++) {
                    mma16816(acc[mt][nt], ahi + mt * 4, bf + nt * 2);
                    mma16816(acc[mt][nt], alo + mt * 4, bf + nt * 2);
                }
            ldsm4(bf,      bLoB + boffL + ko);
            ldsm4(bf + 4,  bLoB + boffL + ko + 16 * 40 * 2);
            ldsm4(bf + 8,  bLoB + boffL + ko + 32 * 40 * 2);
            ldsm4(bf + 12, bLoB + boffL + ko + 48 * 40 * 2);
            #pragma unroll
            for (int mt = 0; mt < 2; mt++)
                #pragma unroll
                for (int nt = 0; nt < 8; nt++)
                    mma16816(acc[mt][nt], ahi + mt * 4, bf + nt * 2);
        }
    }

    // ---- epilogue: add bias, store fp32 ----
    #pragma unroll
    for (int mt = 0; mt < 2; mt++) {
        int r0 = m0 + wm * 32 + mt * 16 + (lane >> 2);
        #pragma unroll
        for (int nt = 0; nt < 8; nt++) {
            int c = wn * 64 + nt * 8 + (lane & 3) * 2;
            float b0 = sBias[c], b1 = sBias[c + 1];
            if (r0 < M) {
                float2 o = make_float2(acc[mt][nt][0] + b0, acc[mt][nt][1] + b1);
                *(float2*)(C + (size_t)r0 * 128 + c) = o;
            }
            if (r0 + 8 < M) {
                float2 o = make_float2(acc[mt][nt][2] + b0, acc[mt][nt][3] + b1);
                *(float2*)(C + (size_t)(r0 + 8) * 128 + c) = o;
            }
        }
    }
}

// =================================================================
// scalar GEMM (projection only, K=64): C = A@W + bias; C2 = copy
// =================================================================
__global__ __launch_bounds__(256) void gemm_kernel(
    const float* __restrict__ A, const float* __restrict__ W,
    const float* __restrict__ bias,
    float* __restrict__ C, float* __restrict__ C2, int M, int K)
{
    constexpr int BM = 128, BN = 128, BK = 16;
    __shared__ __align__(16) float As[BK][BM + 4];
    __shared__ __align__(16) float Bs[BK][BN];

    const int tid = threadIdx.x;
    const int m0 = blockIdx.x * BM;
    const int tx = tid & 15;
    const int ty = tid >> 4;

    float acc[8][8];
    #pragma unroll
    for (int i = 0; i < 8; i++)
        #pragma unroll
        for (int j = 0; j < 8; j++) acc[i][j] = 0.f;

    for (int kb = 0; kb < K; kb += BK) {
        #pragma unroll
        for (int i = 0; i < 2; i++) {
            int idx = tid + i * 256;
            int r = idx >> 2, c4 = idx & 3;
            int gr = m0 + r;
            float4 v = make_float4(0.f, 0.f, 0.f, 0.f);
            if (gr < M) v = *(const float4*)(A + (size_t)gr * K + kb + c4 * 4);
            As[c4 * 4 + 0][r] = v.x;
            As[c4 * 4 + 1][r] = v.y;
            As[c4 * 4 + 2][r] = v.z;
            As[c4 * 4 + 3][r] = v.w;
        }
        #pragma unroll
        for (int i = 0; i < 2; i++) {
            int idx = tid + i * 256;
            int r = idx >> 5, c4 = idx & 31;
            *(float4*)&Bs[r][c4 * 4] =
                *(const float4*)(W + (size_t)(kb + r) * BN + c4 * 4);
        }
        __syncthreads();

        #pragma unroll
        for (int kk = 0; kk < BK; kk++) {
            float4 a0 = *(const float4*)&As[kk][ty * 8];
            float4 a1 = *(const float4*)&As[kk][ty * 8 + 4];
            float4 b0 = *(const float4*)&Bs[kk][tx * 8];
            float4 b1 = *(const float4*)&Bs[kk][tx * 8 + 4];
            float av[8] = {a0.x, a0.y, a0.z, a0.w, a1.x, a1.y, a1.z, a1.w};
            float bv[8] = {b0.x, b0.y, b0.z, b0.w, b1.x, b1.y, b1.z, b1.w};
            #pragma unroll
            for (int i = 0; i < 8; i++)
                #pragma unroll
                for (int j = 0; j < 8; j++)
                    acc[i][j] = fmaf(av[i], bv[j], acc[i][j]);
        }
        __syncthreads();
    }

    float4 bv0 = *(const float4*)(bias + tx * 8);
    float4 bv1 = *(const float4*)(bias + tx * 8 + 4);
    float bb[8] = {bv0.x, bv0.y, bv0.z, bv0.w, bv1.x, bv1.y, bv1.z, bv1.w};

    #pragma unroll
    for (int i = 0; i < 8; i++) {
        int gr = m0 + ty * 8 + i;
        if (gr < M) {
            float4 o0 = make_float4(acc[i][0] + bb[0], acc[i][1] + bb[1],
                                    acc[i][2] + bb[2], acc[i][3] + bb[3]);
            float4 o1 = make_float4(acc[i][4] + bb[4], acc[i][5] + bb[5],
                                    acc[i][6] + bb[6], acc[i][7] + bb[7]);
            *(float4*)(C + (size_t)gr * BN + tx * 8)     = o0;
            *(float4*)(C + (size_t)gr * BN + tx * 8 + 4) = o1;
            if (C2) {
                *(float4*)(C2 + (size_t)gr * BN + tx * 8)     = o0;
                *(float4*)(C2 + (size_t)gr * BN + tx * 8 + 4) = o1;
            }
        }
    }
}

// ---------------- fast column stats: out[0..127]=sum, out[128..255]=sumsq ----------------
__global__ __launch_bounds__(256) void stats_fast(
    const float* __restrict__ T, int M, float* __restrict__ out)
{
    __shared__ float sS[8 * 128];
    __shared__ float sQ[8 * 128];
    const int tid = threadIdx.x, w = tid >> 5, l = tid & 31;
    const int c4 = l * 4;
    float4 s = make_float4(0.f, 0.f, 0.f, 0.f);
    float4 q = make_float4(0.f, 0.f, 0.f, 0.f);
    for (int r = blockIdx.x * 8 + w; r < M; r += gridDim.x * 8) {
        float4 v = *(const float4*)(T + (size_t)r * 128 + c4);
        s.x += v.x; q.x = fmaf(v.x, v.x, q.x);
        s.y += v.y; q.y = fmaf(v.y, v.y, q.y);
        s.z += v.z; q.z = fmaf(v.z, v.z, q.z);
        s.w += v.w; q.w = fmaf(v.w, v.w, q.w);
    }
    *(float4*)&sS[w * 128 + c4] = s;
    *(float4*)&sQ[w * 128 + c4] = q;
    __syncthreads();
    if (tid < 128) {
        float a = 0.f, b = 0.f;
        #pragma unroll
        for (int ww = 0; ww < 8; ww++) {
            a += sS[ww * 128 + tid];
            b += sQ[ww * 128 + tid];
        }
        atomicAdd(&out[tid], a);
        atomicAdd(&out[128 + tid], b);
    }
}

// ---------------- fused edge kernel: agg[dst] += relu(h[src] + edge_attr @ We + be) ----------------
__global__ __launch_bounds__(256) void edge_kernel(
    const float* __restrict__ h, const float* __restrict__ ea,
    const int* __restrict__ src, const int* __restrict__ dst,
    const float* __restrict__ We, const float* __restrict__ be,
    float* __restrict__ agg, int E)
{
    __shared__ __align__(16) float Ws[16][128];
    __shared__ __align__(16) float bs[128];
    const int tid = threadIdx.x;
    for (int i = tid; i < 16 * 128; i += 256) Ws[i >> 7][i & 127] = We[i];
    if (tid < 128) bs[tid] = be[tid];
    __syncthreads();

    const int warp = tid >> 5, lid = tid & 31;
    const int j0 = lid * 4;

    for (int e = blockIdx.x * 8 + warp; e < E; e += gridDim.x * 8) {
        float v = (lid < 16) ? ea[(size_t)e * 16 + lid] : 0.f;
        int s = src[e], d = dst[e];
        float4 acc = *(const float4*)&bs[j0];
        #pragma unroll
        for (int k = 0; k < 16; k++) {
            float a = __shfl_sync(0xffffffffu, v, k);
            float4 w = *(const float4*)&Ws[k][j0];
            acc.x = fmaf(a, w.x, acc.x);
            acc.y = fmaf(a, w.y, acc.y);
            acc.z = fmaf(a, w.z, acc.z);
            acc.w = fmaf(a, w.w, acc.w);
        }
        float4 hv = *(const float4*)(h + (size_t)s * 128 + j0);
        float mx = fmaxf(acc.x + hv.x, 0.f);
        float my = fmaxf(acc.y + hv.y, 0.f);
        float mz = fmaxf(acc.z + hv.z, 0.f);
        float mw = fmaxf(acc.w + hv.w, 0.f);
        float* p = agg + (size_t)d * 128 + j0;
        asm volatile("red.global.add.v4.f32 [%0], {%1,%2,%3,%4};"
                     :: "l"(p), "f"(mx), "f"(my), "f"(mz), "f"(mw) : "memory");
    }
}

// ---------------- bn+relu apply ----------------
__global__ __launch_bounds__(256) void bn_apply_kernel(
    const float* __restrict__ T, const float* __restrict__ gstats,
    const float* __restrict__ gamma, const float* __restrict__ beta, float invM,
    float* __restrict__ outl, float* __restrict__ aggcopy, int total4)
{
    __shared__ float sSc[128];
    __shared__ float sSh[128];
    if (threadIdx.x < 128) {
        int c = threadIdx.x;
        float m = gstats[c] * invM;
        float v = gstats[128 + c] * invM - m * m;
        float sc = gamma[c] * rsqrtf(v + 1e-5f);
        sSc[c] = sc;
        sSh[c] = beta[c] - m * sc;
    }
    __syncthreads();
    int i = blockIdx.x * blockDim.x + threadIdx.x;
    if (i < total4) {
        int c4 = (i & 31) * 4;
        float4 v = *(const float4*)(T + (size_t)i * 4);
        float4 sc = *(const float4*)&sSc[c4];
        float4 sh = *(const float4*)&sSh[c4];
        float4 r;
        r.x = fmaxf(fmaf(v.x, sc.x, sh.x), 0.f);
        r.y = fmaxf(fmaf(v.y, sc.y, sh.y), 0.f);
        r.z = fmaxf(fmaf(v.z, sc.z, sh.z), 0.f);
        r.w = fmaxf(fmaf(v.w, sc.w, sh.w), 0.f);
        *(float4*)(outl + (size_t)i * 4) = r;
        if (aggcopy) *(float4*)(aggcopy + (size_t)i * 4) = r;
    }
}

// ---------------- pooling ----------------
__device__ __forceinline__ int lower_bound_i(const int* a, int n, int key) {
    int lo = 0, hi = n;
    while (lo < hi) { int mid = (lo + hi) >> 1; if (a[mid] < key) lo = mid + 1; else hi = mid; }
    return lo;
}

__global__ __launch_bounds__(384) void pool_kernel(
    const float* __restrict__ o0, const float* __restrict__ o1, const float* __restrict__ o2,
    const int* __restrict__ batch, int Nn, float* __restrict__ zcat)
{
    const int g = blockIdx.x;
    const int lo = lower_bound_i(batch, Nn, g);
    const int hi = lower_bound_i(batch, Nn, g + 1);
    const int c = threadIdx.x;
    const float* src = (c < 128) ? o0 : ((c < 256) ? o1 : o2);
    const int cc = c & 127;
    float s = 0.f, mx = 0.f;
    for (int n = lo; n < hi; n++) {
        float v = src[(size_t)n * 128 + cc];
        s += v; mx = fmaxf(mx, v);
    }
    int cnt = hi - lo;
    float mean = s / (float)(cnt > 0 ? cnt : 1);
    zcat[(size_t)g * 768 + c]       = mean;
    zcat[(size_t)g * 768 + 384 + c] = mx;
}

// ---------------- head ----------------
__global__ __launch_bounds__(128) void head1_kernel(
    const float* __restrict__ zcat, const float* __restrict__ W1,
    const float* __restrict__ b1, float* __restrict__ zh)
{
    __shared__ __align__(16) float zs[768];
    const int g = blockIdx.x;
    for (int k = threadIdx.x; k < 768; k += 128) zs[k] = zcat[(size_t)g * 768 + k];
    __syncthreads();
    const int j = threadIdx.x;
    float acc = b1[j];
    #pragma unroll 8
    for (int k = 0; k < 768; k++) acc = fmaf(zs[k], W1[(size_t)k * 128 + j], acc);
    zh[(size_t)g * 128 + j] = acc;
}

__global__ __launch_bounds__(128) void head_stats_kernel(
    const float* __restrict__ zh, const float* __restrict__ g, const float* __restrict__ b,
    int G, float* __restrict__ sc_sh)
{
    int c = threadIdx.x;
    float s = 0.f, s2 = 0.f;
    for (int r = 0; r < G; r++) { float v = zh[(size_t)r * 128 + c]; s += v; s2 = fmaf(v, v, s2); }
    float invG = 1.f / (float)G;
    float m = s * invG;
    float var = s2 * invG - m * m;
    float sc = g[c] * rsqrtf(var + 1e-5f);
    sc_sh[c] = sc;
    sc_sh[128 + c] = b[c] - m * sc;
}

__global__ __launch_bounds__(128) void head2_kernel(
    const float* __restrict__ zh, const float* __restrict__ sc_sh,
    const float* __restrict__ W2, const float* __restrict__ b2, float* __restrict__ out)
{
    __shared__ float red[128];
    const int g = blockIdx.x, j = threadIdx.x;
    float v = fmaxf(fmaf(zh[(size_t)g * 128 + j], sc_sh[j], sc_sh[128 + j]), 0.f) * W2[j];
    red[j] = v;
    __syncthreads();
    #pragma unroll
    for (int s = 64; s > 0; s >>= 1) {
        if (j < s) red[j] += red[j + s];
        __syncthreads();
    }
    if (j == 0) out[g] = red[0] + b2[0];
}

// ---------------- launcher ----------------
extern "C" void kernel_launch(void* const* d_in, const int* in_sizes, int n_in,
                              void* d_out, int out_size)
{
    const float* x         = (const float*)d_in[0];
    const float* edge_attr = (const float*)d_in[1];
    const int*   src       = (const int*)  d_in[2];
    const int*   dst       = (const int*)  d_in[3];
    const int*   batch     = (const int*)  d_in[4];
    const float* Wp        = (const float*)d_in[5];
    const float* bp        = (const float*)d_in[6];
    const float* conv_We   = (const float*)d_in[7];
    const float* conv_be   = (const float*)d_in[8];
    const float* conv_W1   = (const float*)d_in[9];
    const float* conv_b1   = (const float*)d_in[10];
    const float* conv_g1   = (const float*)d_in[11];
    const float* conv_bt1  = (const float*)d_in[12];
    const float* conv_W2   = (const float*)d_in[13];
    const float* conv_b2   = (const float*)d_in[14];
    const float* bn_g      = (const float*)d_in[15];
    const float* bn_b      = (const float*)d_in[16];
    const float* head_W1   = (const float*)d_in[17];
    const float* head_b1   = (const float*)d_in[18];
    const float* head_g    = (const float*)d_in[19];
    const float* head_bt   = (const float*)d_in[20];
    const float* head_W2   = (const float*)d_in[21];
    const float* head_b2   = (const float*)d_in[22];

    const int Nn = in_sizes[0] / 64;     // 50000
    const int E  = in_sizes[2];          // 800000
    const int G  = out_size;             // 256

    float *hp, *agg, *t, *outl, *zcat, *zh, *stats, *hsc;
    __nv_bfloat16 *whi, *wlo;
    cudaGetSymbolAddress((void**)&hp,    d_hp);
    cudaGetSymbolAddress((void**)&agg,   d_agg);
    cudaGetSymbolAddress((void**)&t,     d_t);
    cudaGetSymbolAddress((void**)&outl,  d_outl);
    cudaGetSymbolAddress((void**)&zcat,  d_zcat);
    cudaGetSymbolAddress((void**)&zh,    d_zh);
    cudaGetSymbolAddress((void**)&stats, d_stats);
    cudaGetSymbolAddress((void**)&hsc,   d_hsc);
    cudaGetSymbolAddress((void**)&whi,   d_whi);
    cudaGetSymbolAddress((void**)&wlo,   d_wlo);

    const int gB = (Nn + 127) / 128;
    const float invM = 1.f / (float)Nn;
    const int total4 = Nn * 32;          // N*128/4

    // zero BN stat accumulators (re-zeroed every launch -> replay-safe)
    cudaMemsetAsync(stats, 0, 6 * 256 * sizeof(float), 0);

    // projection: h = x @ Wp + bp ; also agg = h
    gemm_kernel<<<gB, 256>>>(x, Wp, bp, hp, agg, Nn, 64);

    const float* h = hp;
    for (int l = 0; l < 3; l++) {
        const float* We_l = conv_We + (size_t)l * 16 * 128;
        const float* be_l = conv_be + (size_t)l * 128;
        const float* W1_l = conv_W1 + (size_t)l * 128 * 128;
        const float* b1_l = conv_b1 + (size_t)l * 128;
        const float* g1_l = conv_g1 + (size_t)l * 128;
        const float* t1_l = conv_bt1 + (size_t)l * 128;
        const float* W2_l = conv_W2 + (size_t)l * 128 * 128;
        const float* b2_l = conv_b2 + (size_t)l * 128;
        const float* bg_l = bn_g + (size_t)l * 128;
        const float* bb_l = bn_b + (size_t)l * 128;
        float* outl_l = outl + (size_t)l * Nn * 128;
        float* S0 = stats + (size_t)(2 * l) * 256;
        float* S1 = stats + (size_t)(2 * l + 1) * 256;

        // agg (== h + sum msg after this) via atomic reductions
        edge_kernel<<<4096, 256>>>(h, edge_attr, src, dst, We_l, be_l, agg, E);

        // t1 = agg @ W1 + b1 (HMMA bf16-split)
        conv_w<<<64, 256>>>(W1_l, whi, wlo);
        mma_gemm<<<gB, 256>>>(agg, whi, wlo, b1_l,
                              nullptr, nullptr, nullptr, 0.f, t, Nn);
        stats_fast<<<512, 256>>>(t, Nn, S0);

        // t2 = relu(bn_{S0}(t1)) @ W2 + b2 (in place, HMMA)
        conv_w<<<64, 256>>>(W2_l, whi, wlo);
        mma_gemm<<<gB, 256>>>(t, whi, wlo, b2_l,
                              S0, g1_l, t1_l, invM, t, Nn);
        stats_fast<<<512, 256>>>(t, Nn, S1);

        // out_l = relu(bn_{S1}(t2)) ; also agg = out_l for next layer
        bn_apply_kernel<<<(total4 + 255) / 256, 256>>>(
            t, S1, bg_l, bb_l, invM, outl_l, (l < 2) ? agg : nullptr, total4);

        h = outl_l;
    }

    pool_kernel<<<G, 384>>>(outl, outl + (size_t)Nn * 128, outl + (size_t)2 * Nn * 128,
                            batch, Nn, zcat);
    head1_kernel<<<G, 128>>>(zcat, head_W1, head_b1, zh);
    head_stats_kernel<<<1, 128>>>(zh, head_g, head_bt, G, hsc);
    head2_kernel<<<G, 128>>>(zh, hsc, head_W2, head_b2, (float*)d_out);
}